// round 16
// baseline (speedup 1.0000x reference)
#include <cuda_runtime.h>
#include <cuda_bf16.h>
#include <cuda_fp16.h>
#include <math.h>

#define BB 4
#define SS 2048
#define DD 512
#define HH 8
#define HDIM 64
#define NT (BB*SS)          // 8192 tokens
#define QKVD (3*DD)         // 1536

// ---- scratch (no allocations allowed) ----
__device__ float          g_xn [NT*DD];
__device__ __nv_bfloat16  g_xnh[NT*DD];
__device__ __nv_bfloat16  g_qkv[NT*QKVD];   // ALL fp16 bits (Q pre-scaled)
__device__ __nv_bfloat16  g_att[NT*DD];
__device__ float          g_xr [NT*DD];
__device__ __nv_bfloat16  g_xrh[NT*DD];
__device__ __nv_bfloat16  g_wqkvh[QKVD*DD];
__device__ __nv_bfloat16  g_woh [DD*DD];
__device__ __nv_bfloat16  g_w1h [(DD/2)*DD];

// Q pre-scale folded into QKV epilogue: 1/sqrt(64) * log2(e)
#define QSCALE 0.18033688011112042f

// ---------- helpers ----------
__device__ __forceinline__ unsigned pack_bf(float a, float b){
    __nv_bfloat162 h = __floats2bfloat162_rn(a, b);
    return *(unsigned*)&h;
}
__device__ __forceinline__ unsigned pack_h(float a, float b){
    __half2 h = __floats2half2_rn(a, b);      // a -> low half
    return *(unsigned*)&h;
}
__device__ __forceinline__ unsigned ex2h2(unsigned x){
    unsigned r; asm("ex2.approx.f16x2 %0, %1;" : "=r"(r) : "r"(x)); return r;
}
__device__ __forceinline__ void cpa16(void* dst, const void* src){
    unsigned d = (unsigned)__cvta_generic_to_shared(dst);
    asm volatile("cp.async.cg.shared.global [%0], [%1], 16;" :: "r"(d), "l"(src));
}
__device__ __forceinline__ void cpa_commit(){ asm volatile("cp.async.commit_group;" ::: "memory"); }
__device__ __forceinline__ void cpa_wait1(){ asm volatile("cp.async.wait_group 1;" ::: "memory"); }
__device__ __forceinline__ void mma_bf16(float* c, const unsigned* a, const unsigned* b){
    asm volatile("mma.sync.aligned.m16n8k16.row.col.f32.bf16.bf16.f32 "
        "{%0,%1,%2,%3},{%4,%5,%6,%7},{%8,%9},{%0,%1,%2,%3};"
        : "+f"(c[0]), "+f"(c[1]), "+f"(c[2]), "+f"(c[3])
        : "r"(a[0]), "r"(a[1]), "r"(a[2]), "r"(a[3]), "r"(b[0]), "r"(b[1]));
}
__device__ __forceinline__ void mma_f16(float* c, const unsigned* a, const unsigned* b){
    asm volatile("mma.sync.aligned.m16n8k16.row.col.f32.f16.f16.f32 "
        "{%0,%1,%2,%3},{%4,%5,%6,%7},{%8,%9},{%0,%1,%2,%3};"
        : "+f"(c[0]), "+f"(c[1]), "+f"(c[2]), "+f"(c[3])
        : "r"(a[0]), "r"(a[1]), "r"(a[2]), "r"(a[3]), "r"(b[0]), "r"(b[1]));
}
// f16 accumulator variant: C/D are 2 regs of packed f16x2
__device__ __forceinline__ void mma_f16c16(unsigned* c, const unsigned* a, const unsigned* b){
    asm volatile("mma.sync.aligned.m16n8k16.row.col.f16.f16.f16.f16 "
        "{%0,%1},{%2,%3,%4,%5},{%6,%7},{%0,%1};"
        : "+r"(c[0]), "+r"(c[1])
        : "r"(a[0]), "r"(a[1]), "r"(a[2]), "r"(a[3]), "r"(b[0]), "r"(b[1]));
}
__device__ __forceinline__ void ldsm4(unsigned& r0, unsigned& r1, unsigned& r2, unsigned& r3, const void* p){
    unsigned a = (unsigned)__cvta_generic_to_shared(p);
    asm volatile("ldmatrix.sync.aligned.m8n8.x4.shared.b16 {%0,%1,%2,%3}, [%4];"
        : "=r"(r0), "=r"(r1), "=r"(r2), "=r"(r3) : "r"(a));
}
__device__ __forceinline__ void ldsm4t(unsigned& r0, unsigned& r1, unsigned& r2, unsigned& r3, const void* p){
    unsigned a = (unsigned)__cvta_generic_to_shared(p);
    asm volatile("ldmatrix.sync.aligned.m8n8.x4.trans.shared.b16 {%0,%1,%2,%3}, [%4];"
        : "=r"(r0), "=r"(r1), "=r"(r2), "=r"(r3) : "r"(a));
}

// ============================================================
// 0) fused fp32 -> bf16 weight conversion (all three weights)
// ============================================================
#define NW1 (QKVD*DD/4)
#define NW2 (DD*DD/4)
#define NW3 ((DD/2)*DD/4)
__global__ __launch_bounds__(256)
void cvt_all(const float4* __restrict__ s1, const float4* __restrict__ s2,
             const float4* __restrict__ s3){
    int i = blockIdx.x*256 + threadIdx.x;
    uint2* d1 = (uint2*)g_wqkvh; uint2* d2 = (uint2*)g_woh; uint2* d3 = (uint2*)g_w1h;
    if (i < NW1){
        float4 v = s1[i];
        d1[i] = make_uint2(pack_bf(v.x,v.y), pack_bf(v.z,v.w));
    } else if (i < NW1+NW2){
        float4 v = s2[i-NW1];
        d2[i-NW1] = make_uint2(pack_bf(v.x,v.y), pack_bf(v.z,v.w));
    } else if (i < NW1+NW2+NW3){
        float4 v = s3[i-NW1-NW2];
        d3[i-NW1-NW2] = make_uint2(pack_bf(v.x,v.y), pack_bf(v.z,v.w));
    }
}

// ============================================================
// 1) conditional LayerNorm (writes fp32 + bf16 copies)
// ============================================================
__global__ __launch_bounds__(128)
void ln_kernel(const float* __restrict__ x, const int* __restrict__ gt,
               const float* __restrict__ tfg, const float* __restrict__ tfb,
               const float* __restrict__ tgg, const float* __restrict__ tgb) {
    int t = blockIdx.x;
    int tid = threadIdx.x;
    const float4 v = ((const float4*)(x + (size_t)t*DD))[tid];
    float s  = v.x+v.y+v.z+v.w;
    float sq = v.x*v.x+v.y*v.y+v.z*v.z+v.w*v.w;
    #pragma unroll
    for (int o=16;o;o>>=1){ s += __shfl_xor_sync(~0u,s,o); sq += __shfl_xor_sync(~0u,sq,o); }
    __shared__ float sh[8];
    int w = tid>>5, l = tid&31;
    if (l==0){ sh[w]=s; sh[4+w]=sq; }
    __syncthreads();
    if (tid==0){
        float S=sh[0]+sh[1]+sh[2]+sh[3], Q=sh[4]+sh[5]+sh[6]+sh[7];
        float mu = S/(float)DD;
        float var = Q/(float)DD - mu*mu;
        sh[0]=mu; sh[1]=rsqrtf(var + 1e-5f);
    }
    __syncthreads();
    float mu = sh[0], rs = sh[1];
    int g = gt[t];
    float4 out;
    if (g==0 || g==1){
        const float* gp = (g==0)? tfg : tgg;
        const float* bp = (g==0)? tfb : tgb;
        float4 gv = ((const float4*)gp)[tid];
        float4 bv = ((const float4*)bp)[tid];
        out.x = (v.x-mu)*rs*gv.x + bv.x;
        out.y = (v.y-mu)*rs*gv.y + bv.y;
        out.z = (v.z-mu)*rs*gv.z + bv.z;
        out.w = (v.w-mu)*rs*gv.w + bv.w;
    } else {
        out = v;
    }
    ((float4*)(g_xn + (size_t)t*DD))[tid] = out;
    ((uint2*)(g_xnh + (size_t)t*DD))[tid] = make_uint2(pack_bf(out.x,out.y), pack_bf(out.z,out.w));
}

// ============================================================
// 2) bf16 GEMM, 3-stage cp.async: C = A[M,K]·B[N,K]^T
//    EPI 0: bias -> Cb as fp16 (Q cols scaled by QSCALE)
//    EPI 1: bias+res -> Cf + Cb (bf16)
// ============================================================
#define GP 40   // smem pitch in halfs
#define GEMM_SMEM (2*3*128*GP*2)
template<int EPI>
__global__ __launch_bounds__(256)
void gemm_bf(const __nv_bfloat16* __restrict__ A, const __nv_bfloat16* __restrict__ B,
             const float* __restrict__ bias, const float* __restrict__ res,
             float* __restrict__ Cf, __nv_bfloat16* __restrict__ Cb, int N, int K) {
    extern __shared__ __align__(16) char dyn[];
    __nv_bfloat16* As = (__nv_bfloat16*)dyn;
    __nv_bfloat16* Bs = As + 3*128*GP;
    int tid = threadIdx.x;
    int w = tid>>5, lane = tid&31;
    int qr = lane>>2, qc = lane&3;
    int wy = w>>1, wx = w&1;
    int m0 = blockIdx.y*128, n0 = blockIdx.x*128;
    int lr = tid>>1, lh = tid&1;
    int lmr = lane & 15, lmc = lane >> 4;

    float acc[2][8][4];
    #pragma unroll
    for (int i=0;i<2;i++)
        #pragma unroll
        for (int j=0;j<8;j++)
            #pragma unroll
            for (int k=0;k<4;k++) acc[i][j][k]=0.f;

    const int NIT = K/32;
    auto load_stage = [&](int s, int b){
        int k0 = s*32;
        const __nv_bfloat16* ap = A + (size_t)(m0+lr)*K + k0 + lh*16;
        const __nv_bfloat16* bp = B + (size_t)(n0+lr)*K + k0 + lh*16;
        __nv_bfloat16* ad = As + b*128*GP + lr*GP + lh*16;
        __nv_bfloat16* bd = Bs + b*128*GP + lr*GP + lh*16;
        cpa16(ad,   ap);   cpa16(ad+8, ap+8);
        cpa16(bd,   bp);   cpa16(bd+8, bp+8);
        cpa_commit();
    };
    load_stage(0, 0);
    load_stage(1, 1);

    for (int it = 0; it < NIT; it++) {
        int cur = it % 3;
        cpa_wait1();
        __syncthreads();
        if (it+2 < NIT) load_stage(it+2, (it+2)%3);
        else            cpa_commit();
        const __nv_bfloat16* Ab = As + cur*128*GP;
        const __nv_bfloat16* Bb = Bs + cur*128*GP;
        #pragma unroll
        for (int ks=0; ks<2; ks++) {
            int kb = ks*16;
            unsigned af[2][4], bf[8][2];
            #pragma unroll
            for (int mt=0; mt<2; mt++)
                ldsm4(af[mt][0], af[mt][1], af[mt][2], af[mt][3],
                      &Ab[(wy*32 + mt*16 + lmr)*GP + kb + lmc*8]);
            #pragma unroll
            for (int ng=0; ng<4; ng++){
                unsigned r0,r1,r2,r3;
                ldsm4(r0,r1,r2,r3, &Bb[(wx*64 + ng*16 + lmr)*GP + kb + lmc*8]);
                bf[2*ng  ][0]=r0; bf[2*ng  ][1]=r2;
                bf[2*ng+1][0]=r1; bf[2*ng+1][1]=r3;
            }
            #pragma unroll
            for (int mt=0; mt<2; mt++)
                #pragma unroll
                for (int nt=0; nt<8; nt++)
                    mma_bf16(acc[mt][nt], af[mt], bf[nt]);
        }
    }
    #pragma unroll
    for (int mt=0; mt<2; mt++){
        #pragma unroll
        for (int nt=0; nt<8; nt++){
            int gr = m0 + wy*32 + mt*16 + qr;
            int gc = n0 + wx*64 + nt*8 + 2*qc;
            float bx = bias[gc], by = bias[gc+1];
            float c0 = acc[mt][nt][0]+bx, c1 = acc[mt][nt][1]+by;
            float c2 = acc[mt][nt][2]+bx, c3 = acc[mt][nt][3]+by;
            if (EPI==0){
                if (gc < DD){ c0*=QSCALE; c1*=QSCALE; c2*=QSCALE; c3*=QSCALE; }
                *(unsigned*)(Cb + (size_t)gr*N + gc)     = pack_h(c0,c1);
                *(unsigned*)(Cb + (size_t)(gr+8)*N + gc) = pack_h(c2,c3);
            }
            if (EPI==1){
                const float* r0 = res + (size_t)gr*N + gc;
                const float* r1 = res + (size_t)(gr+8)*N + gc;
                c0 += r0[0]; c1 += r0[1]; c2 += r1[0]; c3 += r1[1];
                float2 v0 = {c0,c1}, v1 = {c2,c3};
                *(float2*)(Cf + (size_t)gr*N + gc)     = v0;
                *(float2*)(Cf + (size_t)(gr+8)*N + gc) = v1;
                *(unsigned*)(Cb + (size_t)gr*N + gc)     = pack_bf(c0,c1);
                *(unsigned*)(Cb + (size_t)(gr+8)*N + gc) = pack_bf(c2,c3);
            }
        }
    }
}

// ============================================================
// 3) flash attention (R14 core, per-batch launch):
//    8 warps x 16 q-rows (256 thr), 64-key tiles, 3-stage cp.async,
//    S-MMA f16 acc -> ex2.f16x2 in place -> O-MMA f32 acc,
//    row sums via constant-ones B-fragment.
// ============================================================
#define AP 72
#define ATTN_SMEM (2*3*64*AP*2)
__global__ __launch_bounds__(256, 3)
void attn_bf(int bsel) {
    extern __shared__ __align__(16) char dyn[];
    __nv_bfloat16* KsB = (__nv_bfloat16*)dyn;       // 3 x 64*AP  (K tiles)
    __nv_bfloat16* VsB = KsB + 3*64*AP;             // 3 x 64*AP  (V tiles)
    const __nv_bfloat16* qkv = g_qkv;
    int tid = threadIdx.x;
    int w = tid>>5, lane = tid&31;
    int qr = lane>>2, qc = lane&3;
    int lmr = lane & 15, lmc = lane >> 4;
    int h = blockIdx.y;
    int q0 = blockIdx.x*128;
    size_t base = (size_t)bsel*SS*QKVD + (size_t)h*HDIM;

    // stage Q (128 rows) through buffer 0 of both arrays, pull frags
    {
        int lr = tid>>1, lh = tid&1;
        const uint4* qp = (const uint4*)(qkv + base + (size_t)(q0+lr)*QKVD + lh*32);
        uint4 v0 = qp[0], v1 = qp[1], v2 = qp[2], v3 = qp[3];
        __nv_bfloat16* dst = (lr < 64) ? &KsB[lr*AP + lh*32] : &VsB[(lr-64)*AP + lh*32];
        uint4* d = (uint4*)dst;
        d[0]=v0; d[1]=v1; d[2]=v2; d[3]=v3;
    }
    __syncthreads();
    unsigned qa[4][4];
    {
        const __nv_bfloat16* qbuf = (w < 4) ? KsB : VsB;
        int row16 = (w&3)*16;
        #pragma unroll
        for (int kc=0; kc<4; kc++)
            ldsm4(qa[kc][0], qa[kc][1], qa[kc][2], qa[kc][3],
                  &qbuf[(row16 + lmr)*AP + kc*16 + lmc*8]);
    }
    __syncthreads();

    float o[8][4];
    #pragma unroll
    for (int nt=0; nt<8; nt++){ o[nt][0]=0.f;o[nt][1]=0.f;o[nt][2]=0.f;o[nt][3]=0.f; }
    float lacc[4] = {0.f, 0.f, 0.f, 0.f};
    // constant ones B-fragment: column n=0 all-ones (lanes 0-3), rest zero
    unsigned bones = (lane < 4) ? 0x3C003C00u : 0u;
    unsigned bs[2] = {bones, bones};

    int kv  = tid >> 7;
    int krow = (tid & 127) >> 1;
    int khalf = tid & 1;
    size_t kvbase = base + (size_t)(1+kv)*DD;

    auto load_kv = [&](int kt, int bix){
        const __nv_bfloat16* src = qkv + kvbase + (size_t)(kt*64 + krow)*QKVD + khalf*32;
        __nv_bfloat16* dst = kv ? &VsB[bix*64*AP + krow*AP + khalf*32]
                                : &KsB[bix*64*AP + krow*AP + khalf*32];
        #pragma unroll
        for (int j=0;j<4;j++) cpa16(dst + j*8, src + j*8);
        cpa_commit();
    };
    load_kv(0, 0);
    load_kv(1, 1);

    const int NKT = SS/64;
    for (int kt=0; kt<NKT; kt++){
        int cur = kt % 3;
        cpa_wait1();
        __syncthreads();
        if (kt+2 < NKT) load_kv(kt+2, (kt+2)%3);
        else            cpa_commit();
        const __nv_bfloat16* Ks = KsB + cur*64*AP;
        const __nv_bfloat16* Vs = VsB + cur*64*AP;

        // S in f16 accumulator
        unsigned sacc[8][2];
        #pragma unroll
        for (int nt=0; nt<8; nt++){ sacc[nt][0]=0u; sacc[nt][1]=0u; }
        #pragma unroll
        for (int kc=0; kc<4; kc++){
            #pragma unroll
            for (int ng=0; ng<4; ng++){
                unsigned r0,r1,r2,r3;
                ldsm4(r0,r1,r2,r3, &Ks[(ng*16 + lmr)*AP + kc*16 + lmc*8]);
                unsigned bfa[2] = {r0, r2};
                unsigned bfb[2] = {r1, r3};
                mma_f16c16(sacc[2*ng  ], qa[kc], bfa);
                mma_f16c16(sacc[2*ng+1], qa[kc], bfb);
            }
        }
        // P = 2^S in place (output is directly the O-MMA A-fragment)
        #pragma unroll
        for (int nt=0; nt<8; nt++){
            sacc[nt][0] = ex2h2(sacc[nt][0]);
            sacc[nt][1] = ex2h2(sacc[nt][1]);
        }
        // O += P·V (f16 in, f32 acc); row sums via bones fragment
        #pragma unroll
        for (int kc=0; kc<4; kc++){
            unsigned pa[4];
            pa[0] = sacc[2*kc  ][0];
            pa[1] = sacc[2*kc  ][1];
            pa[2] = sacc[2*kc+1][0];
            pa[3] = sacc[2*kc+1][1];
            #pragma unroll
            for (int ng=0; ng<4; ng++){
                unsigned r0,r1,r2,r3;
                ldsm4t(r0,r1,r2,r3,
                       &Vs[(kc*16 + ((lane>>3)&1)*8 + (lane&7))*AP + ng*16 + (lane>>4)*8]);
                unsigned bfa[2] = {r0, r1};
                unsigned bfb[2] = {r2, r3};
                mma_f16(o[2*ng  ], pa, bfa);
                mma_f16(o[2*ng+1], pa, bfb);
            }
            mma_f16(lacc, pa, bs);
        }
    }
    // row sums live in column 0 (qc==0 lanes); broadcast
    float l0 = __shfl_sync(~0u, lacc[0], lane & ~3);
    float l1 = __shfl_sync(~0u, lacc[2], lane & ~3);
    float i0 = 1.f/l0, i1 = 1.f/l1;
    int sr = q0 + w*16 + qr;
    __nv_bfloat16* op = g_att + (size_t)(bsel*SS + sr)*DD + h*HDIM;
    #pragma unroll
    for (int nt=0; nt<8; nt++){
        *(unsigned*)(op + nt*8 + 2*qc)        = pack_bf(o[nt][0]*i0, o[nt][1]*i0);
        *(unsigned*)(op + 8*DD + nt*8 + 2*qc) = pack_bf(o[nt][2]*i1, o[nt][3]*i1);
    }
}

// ============================================================
// 4) fused MLP + gate, 32-row blocks:
//    h = silu(xr@W1^T + b1) in regs, strength = sigmoid(h.w2+b2),
//    out = xr * strength. 256 threads = 8 warps, warp tile 32x32.
// ============================================================
#define MLP_SMEM (3*32*GP*2 + 3*256*GP*2)
__global__ __launch_bounds__(256)
void mlp_gate(const __nv_bfloat16* __restrict__ A, const __nv_bfloat16* __restrict__ B,
              const float* __restrict__ b1, const float* __restrict__ w2,
              const float* __restrict__ b2, const float* __restrict__ xr,
              float* __restrict__ out) {
    extern __shared__ __align__(16) char dyn[];
    __nv_bfloat16* As = (__nv_bfloat16*)dyn;       // 3 x 32*GP
    __nv_bfloat16* Bs = As + 3*32*GP;              // 3 x 256*GP
    __shared__ float red[32][8];
    __shared__ float sgate_s[32];
    int tid = threadIdx.x;
    int w = tid>>5, lane = tid&31;
    int qr = lane>>2, qc = lane&3;
    int wx = w;                        // 8 warps across N (8 x 32 = 256 cols)
    int lmr = lane & 15, lmc = lane >> 4;
    int m0 = blockIdx.x*32;

    float acc[2][4][4];
    #pragma unroll
    for (int i=0;i<2;i++)
        #pragma unroll
        for (int j=0;j<4;j++)
            #pragma unroll
            for (int k=0;k<4;k++) acc[i][j][k]=0.f;

    auto load_stage = [&](int s, int bix){
        int k0 = s*32;
        #pragma unroll
        for (int i=0;i<2;i++){       // B: 256 rows x 2 halves = 512 chunks
            int c = tid + i*256;
            int row = c>>1, half = c&1;
            const __nv_bfloat16* bp = B + (size_t)row*DD + k0 + half*16;
            __nv_bfloat16* d = Bs + bix*256*GP + row*GP + half*16;
            cpa16(d, bp); cpa16(d+8, bp+8);
        }
        if (tid < 64){               // A: 32 rows x 2 halves = 64 chunks
            int row = tid>>1, half = tid&1;
            const __nv_bfloat16* ap = A + (size_t)(m0+row)*DD + k0 + half*16;
            __nv_bfloat16* d = As + bix*32*GP + row*GP + half*16;
            cpa16(d, ap); cpa16(d+8, ap+8);
        }
        cpa_commit();
    };
    load_stage(0, 0);
    load_stage(1, 1);

    const int NIT = DD/32;
    for (int it = 0; it < NIT; it++){
        int cur = it % 3;
        cpa_wait1();
        __syncthreads();
        if (it+2 < NIT) load_stage(it+2, (it+2)%3);
        else            cpa_commit();
        const __nv_bfloat16* Ab = As + cur*32*GP;
        const __nv_bfloat16* Bb = Bs + cur*256*GP;
        #pragma unroll
        for (int ks=0; ks<2; ks++){
            int kb = ks*16;
            unsigned af[2][4], bf[4][2];
            #pragma unroll
            for (int mt=0; mt<2; mt++)
                ldsm4(af[mt][0], af[mt][1], af[mt][2], af[mt][3],
                      &Ab[(mt*16 + lmr)*GP + kb + lmc*8]);
            #pragma unroll
            for (int ng=0; ng<2; ng++){
                unsigned r0,r1,r2,r3;
                ldsm4(r0,r1,r2,r3, &Bb[(wx*32 + ng*16 + lmr)*GP + kb + lmc*8]);
                bf[2*ng  ][0]=r0; bf[2*ng  ][1]=r2;
                bf[2*ng+1][0]=r1; bf[2*ng+1][1]=r3;
            }
            #pragma unroll
            for (int mt=0; mt<2; mt++)
                #pragma unroll
                for (int nt=0; nt<4; nt++)
                    mma_bf16(acc[mt][nt], af[mt], bf[nt]);
        }
    }

    #pragma unroll
    for (int mt=0; mt<2; mt++){
        float p0 = 0.f, p1 = 0.f;
        #pragma unroll
        for (int nt=0; nt<4; nt++){
            int gc = wx*32 + nt*8 + 2*qc;
            float w0 = w2[gc], w1v = w2[gc+1];
            float bx = b1[gc], by = b1[gc+1];
            float v0 = acc[mt][nt][0]+bx, v1 = acc[mt][nt][1]+by;
            float v2 = acc[mt][nt][2]+bx, v3 = acc[mt][nt][3]+by;
            v0 = v0/(1.f+__expf(-v0)); v1 = v1/(1.f+__expf(-v1));
            v2 = v2/(1.f+__expf(-v2)); v3 = v3/(1.f+__expf(-v3));
            p0 += v0*w0 + v1*w1v;
            p1 += v2*w0 + v3*w1v;
        }
        p0 += __shfl_xor_sync(~0u, p0, 1); p0 += __shfl_xor_sync(~0u, p0, 2);
        p1 += __shfl_xor_sync(~0u, p1, 1); p1 += __shfl_xor_sync(~0u, p1, 2);
        if (qc==0){
            red[mt*16 + qr][wx]     = p0;
            red[mt*16 + qr + 8][wx] = p1;
        }
    }
    __syncthreads();
    if (tid < 32){
        float tot = 0.f;
        #pragma unroll
        for (int j=0;j<8;j++) tot += red[tid][j];
        sgate_s[tid] = 1.f / (1.f + __expf(-(tot + b2[0])));
    }
    __syncthreads();
    {
        int row = tid>>3, seg = (tid&7)*64;   // 32 rows x 8 segs
        float sg = sgate_s[row];
        const float4* xp = (const float4*)(xr + (size_t)(m0+row)*DD + seg);
        float4* op = (float4*)(out + (size_t)(m0+row)*DD + seg);
        #pragma unroll
        for (int i=0;i<16;i++){
            float4 v = xp[i];
            op[i] = make_float4(v.x*sg, v.y*sg, v.z*sg, v.w*sg);
        }
    }
}

// ============================================================
extern "C" void kernel_launch(void* const* d_in, const int* in_sizes, int n_in,
                              void* d_out, int out_size) {
    const float* x    = (const float*)d_in[0];
    const int*   gt   = (const int*)  d_in[1];
    const float* tf_g = (const float*)d_in[2];
    const float* tf_b = (const float*)d_in[3];
    const float* tg_g = (const float*)d_in[4];
    const float* tg_b = (const float*)d_in[5];
    const float* Wqkv = (const float*)d_in[6];
    const float* bqkv = (const float*)d_in[7];
    const float* Wo   = (const float*)d_in[8];
    const float* bo   = (const float*)d_in[9];
    const float* W1   = (const float*)d_in[10];
    const float* b1   = (const float*)d_in[11];
    const float* w2   = (const float*)d_in[12];
    const float* b2   = (const float*)d_in[13];
    float* out = (float*)d_out;

    float *xn, *xr;
    __nv_bfloat16 *xnh, *qkvp, *att, *xrh, *wqkvh, *woh, *w1h;
    cudaGetSymbolAddress((void**)&xn,    g_xn);
    cudaGetSymbolAddress((void**)&xnh,   g_xnh);
    cudaGetSymbolAddress((void**)&qkvp,  g_qkv);
    cudaGetSymbolAddress((void**)&att,   g_att);
    cudaGetSymbolAddress((void**)&xr,    g_xr);
    cudaGetSymbolAddress((void**)&xrh,   g_xrh);
    cudaGetSymbolAddress((void**)&wqkvh, g_wqkvh);
    cudaGetSymbolAddress((void**)&woh,   g_woh);
    cudaGetSymbolAddress((void**)&w1h,   g_w1h);

    static bool init_done = false;
    static cudaStream_t sA, sB;
    static cudaEvent_t evFork, evLn, evCvt, evA, evB;
    if (!init_done){
        cudaFuncSetAttribute(gemm_bf<0>, cudaFuncAttributeMaxDynamicSharedMemorySize, GEMM_SMEM);
        cudaFuncSetAttribute(gemm_bf<1>, cudaFuncAttributeMaxDynamicSharedMemorySize, GEMM_SMEM);
        cudaFuncSetAttribute(attn_bf,    cudaFuncAttributeMaxDynamicSharedMemorySize, ATTN_SMEM);
        cudaFuncSetAttribute(mlp_gate,   cudaFuncAttributeMaxDynamicSharedMemorySize, MLP_SMEM);
        cudaStreamCreateWithFlags(&sA, cudaStreamNonBlocking);
        cudaStreamCreateWithFlags(&sB, cudaStreamNonBlocking);
        cudaEventCreateWithFlags(&evFork, cudaEventDisableTiming);
        cudaEventCreateWithFlags(&evLn,   cudaEventDisableTiming);
        cudaEventCreateWithFlags(&evCvt,  cudaEventDisableTiming);
        cudaEventCreateWithFlags(&evA,    cudaEventDisableTiming);
        cudaEventCreateWithFlags(&evB,    cudaEventDisableTiming);
        init_done = true;
    }

    // fork from the (capture) default stream onto sA / sB
    cudaEventRecord(evFork, 0);
    cudaStreamWaitEvent(sA, evFork, 0);
    cudaStreamWaitEvent(sB, evFork, 0);

    // LN on sA, weight conversion on sB (independent)
    ln_kernel<<<NT, 128, 0, sA>>>(x, gt, tf_g, tf_b, tg_g, tg_b);
    cvt_all<<<(NW1+NW2+NW3 + 255)/256, 256, 0, sB>>>((const float4*)Wqkv, (const float4*)Wo, (const float4*)W1);
    cudaEventRecord(evLn, sA);
    cudaEventRecord(evCvt, sB);
    cudaStreamWaitEvent(sA, evCvt, 0);   // sA now has ln+cvt done
    cudaStreamWaitEvent(sB, evLn, 0);    // sB now has ln+cvt done

    // per-batch chains: b0,b2 on sA; b1,b3 on sB
    for (int b = 0; b < BB; b++){
        cudaStream_t s = (b & 1) ? sB : sA;
        size_t t0 = (size_t)b * SS;
        gemm_bf<0><<<dim3(QKVD/128, SS/128), 256, GEMM_SMEM, s>>>(
            xnh + t0*DD, wqkvh, bqkv, nullptr, nullptr, qkvp + t0*QKVD, QKVD, DD);
        attn_bf<<<dim3(SS/128, HH), 256, ATTN_SMEM, s>>>(b);
        gemm_bf<1><<<dim3(DD/128, SS/128), 256, GEMM_SMEM, s>>>(
            att + t0*DD, woh, bo, xn + t0*DD, xr + t0*DD, xrh + t0*DD, DD, DD);
        mlp_gate<<<SS/32, 256, MLP_SMEM, s>>>(
            xrh + t0*DD, w1h, b1, w2, b2, xr + t0*DD, out + t0*DD);
    }

    // join back into the default (capture) stream
    cudaEventRecord(evA, sA);
    cudaEventRecord(evB, sB);
    cudaStreamWaitEvent(0, evA, 0);
    cudaStreamWaitEvent(0, evB, 0);
}

// round 17
// speedup vs baseline: 1.1509x; 1.1509x over previous
#include <cuda_runtime.h>
#include <cuda_bf16.h>
#include <cuda_fp16.h>
#include <math.h>

#define BB 4
#define SS 2048
#define DD 512
#define HH 8
#define HDIM 64
#define NT (BB*SS)          // 8192 tokens
#define QKVD (3*DD)         // 1536

// ---- scratch (no allocations allowed) ----
__device__ float          g_xn [NT*DD];
__device__ __nv_bfloat16  g_xnh[NT*DD];
__device__ __nv_bfloat16  g_qkv[NT*QKVD];   // ALL fp16 bits (Q pre-scaled)
__device__ __nv_bfloat16  g_att[NT*DD];
__device__ float          g_xr [NT*DD];
__device__ __nv_bfloat16  g_xrh[NT*DD];
__device__ __nv_bfloat16  g_wqkvh[QKVD*DD];
__device__ __nv_bfloat16  g_woh [DD*DD];
__device__ __nv_bfloat16  g_w1h [(DD/2)*DD];

// Q pre-scale folded into QKV epilogue: 1/sqrt(64) * log2(e)
#define QSCALE 0.18033688011112042f

// ---------- helpers ----------
__device__ __forceinline__ unsigned pack_bf(float a, float b){
    __nv_bfloat162 h = __floats2bfloat162_rn(a, b);
    return *(unsigned*)&h;
}
__device__ __forceinline__ unsigned pack_h(float a, float b){
    __half2 h = __floats2half2_rn(a, b);      // a -> low half
    return *(unsigned*)&h;
}
__device__ __forceinline__ unsigned ex2h2(unsigned x){
    unsigned r; asm("ex2.approx.f16x2 %0, %1;" : "=r"(r) : "r"(x)); return r;
}
__device__ __forceinline__ void cpa16(void* dst, const void* src){
    unsigned d = (unsigned)__cvta_generic_to_shared(dst);
    asm volatile("cp.async.cg.shared.global [%0], [%1], 16;" :: "r"(d), "l"(src));
}
__device__ __forceinline__ void cpa_commit(){ asm volatile("cp.async.commit_group;" ::: "memory"); }
__device__ __forceinline__ void cpa_wait1(){ asm volatile("cp.async.wait_group 1;" ::: "memory"); }
__device__ __forceinline__ void mma_bf16(float* c, const unsigned* a, const unsigned* b){
    asm volatile("mma.sync.aligned.m16n8k16.row.col.f32.bf16.bf16.f32 "
        "{%0,%1,%2,%3},{%4,%5,%6,%7},{%8,%9},{%0,%1,%2,%3};"
        : "+f"(c[0]), "+f"(c[1]), "+f"(c[2]), "+f"(c[3])
        : "r"(a[0]), "r"(a[1]), "r"(a[2]), "r"(a[3]), "r"(b[0]), "r"(b[1]));
}
__device__ __forceinline__ void mma_f16(float* c, const unsigned* a, const unsigned* b){
    asm volatile("mma.sync.aligned.m16n8k16.row.col.f32.f16.f16.f32 "
        "{%0,%1,%2,%3},{%4,%5,%6,%7},{%8,%9},{%0,%1,%2,%3};"
        : "+f"(c[0]), "+f"(c[1]), "+f"(c[2]), "+f"(c[3])
        : "r"(a[0]), "r"(a[1]), "r"(a[2]), "r"(a[3]), "r"(b[0]), "r"(b[1]));
}
// f16 accumulator variant: C/D are 2 regs of packed f16x2
__device__ __forceinline__ void mma_f16c16(unsigned* c, const unsigned* a, const unsigned* b){
    asm volatile("mma.sync.aligned.m16n8k16.row.col.f16.f16.f16.f16 "
        "{%0,%1},{%2,%3,%4,%5},{%6,%7},{%0,%1};"
        : "+r"(c[0]), "+r"(c[1])
        : "r"(a[0]), "r"(a[1]), "r"(a[2]), "r"(a[3]), "r"(b[0]), "r"(b[1]));
}
__device__ __forceinline__ void ldsm4(unsigned& r0, unsigned& r1, unsigned& r2, unsigned& r3, const void* p){
    unsigned a = (unsigned)__cvta_generic_to_shared(p);
    asm volatile("ldmatrix.sync.aligned.m8n8.x4.shared.b16 {%0,%1,%2,%3}, [%4];"
        : "=r"(r0), "=r"(r1), "=r"(r2), "=r"(r3) : "r"(a));
}
__device__ __forceinline__ void ldsm4t(unsigned& r0, unsigned& r1, unsigned& r2, unsigned& r3, const void* p){
    unsigned a = (unsigned)__cvta_generic_to_shared(p);
    asm volatile("ldmatrix.sync.aligned.m8n8.x4.trans.shared.b16 {%0,%1,%2,%3}, [%4];"
        : "=r"(r0), "=r"(r1), "=r"(r2), "=r"(r3) : "r"(a));
}

// ============================================================
// 0) fused fp32 -> bf16 weight conversion (all three weights)
// ============================================================
#define NW1 (QKVD*DD/4)
#define NW2 (DD*DD/4)
#define NW3 ((DD/2)*DD/4)
__global__ __launch_bounds__(256)
void cvt_all(const float4* __restrict__ s1, const float4* __restrict__ s2,
             const float4* __restrict__ s3){
    int i = blockIdx.x*256 + threadIdx.x;
    uint2* d1 = (uint2*)g_wqkvh; uint2* d2 = (uint2*)g_woh; uint2* d3 = (uint2*)g_w1h;
    if (i < NW1){
        float4 v = s1[i];
        d1[i] = make_uint2(pack_bf(v.x,v.y), pack_bf(v.z,v.w));
    } else if (i < NW1+NW2){
        float4 v = s2[i-NW1];
        d2[i-NW1] = make_uint2(pack_bf(v.x,v.y), pack_bf(v.z,v.w));
    } else if (i < NW1+NW2+NW3){
        float4 v = s3[i-NW1-NW2];
        d3[i-NW1-NW2] = make_uint2(pack_bf(v.x,v.y), pack_bf(v.z,v.w));
    }
}

// ============================================================
// 1) conditional LayerNorm (writes fp32 + bf16 copies)
// ============================================================
__global__ __launch_bounds__(128)
void ln_kernel(const float* __restrict__ x, const int* __restrict__ gt,
               const float* __restrict__ tfg, const float* __restrict__ tfb,
               const float* __restrict__ tgg, const float* __restrict__ tgb) {
    int t = blockIdx.x;
    int tid = threadIdx.x;
    const float4 v = ((const float4*)(x + (size_t)t*DD))[tid];
    float s  = v.x+v.y+v.z+v.w;
    float sq = v.x*v.x+v.y*v.y+v.z*v.z+v.w*v.w;
    #pragma unroll
    for (int o=16;o;o>>=1){ s += __shfl_xor_sync(~0u,s,o); sq += __shfl_xor_sync(~0u,sq,o); }
    __shared__ float sh[8];
    int w = tid>>5, l = tid&31;
    if (l==0){ sh[w]=s; sh[4+w]=sq; }
    __syncthreads();
    if (tid==0){
        float S=sh[0]+sh[1]+sh[2]+sh[3], Q=sh[4]+sh[5]+sh[6]+sh[7];
        float mu = S/(float)DD;
        float var = Q/(float)DD - mu*mu;
        sh[0]=mu; sh[1]=rsqrtf(var + 1e-5f);
    }
    __syncthreads();
    float mu = sh[0], rs = sh[1];
    int g = gt[t];
    float4 out;
    if (g==0 || g==1){
        const float* gp = (g==0)? tfg : tgg;
        const float* bp = (g==0)? tfb : tgb;
        float4 gv = ((const float4*)gp)[tid];
        float4 bv = ((const float4*)bp)[tid];
        out.x = (v.x-mu)*rs*gv.x + bv.x;
        out.y = (v.y-mu)*rs*gv.y + bv.y;
        out.z = (v.z-mu)*rs*gv.z + bv.z;
        out.w = (v.w-mu)*rs*gv.w + bv.w;
    } else {
        out = v;
    }
    ((float4*)(g_xn + (size_t)t*DD))[tid] = out;
    ((uint2*)(g_xnh + (size_t)t*DD))[tid] = make_uint2(pack_bf(out.x,out.y), pack_bf(out.z,out.w));
}

// ============================================================
// 2) bf16 GEMM, 3-stage cp.async: C = A[M,K]·B[N,K]^T
//    EPI 0: bias -> Cb as fp16 (Q cols scaled by QSCALE)
//    EPI 1: bias+res -> Cf + Cb (bf16)
// ============================================================
#define GP 40   // smem pitch in halfs
#define GEMM_SMEM (2*3*128*GP*2)
template<int EPI>
__global__ __launch_bounds__(256)
void gemm_bf(const __nv_bfloat16* __restrict__ A, const __nv_bfloat16* __restrict__ B,
             const float* __restrict__ bias, const float* __restrict__ res,
             float* __restrict__ Cf, __nv_bfloat16* __restrict__ Cb, int N, int K) {
    extern __shared__ __align__(16) char dyn[];
    __nv_bfloat16* As = (__nv_bfloat16*)dyn;
    __nv_bfloat16* Bs = As + 3*128*GP;
    int tid = threadIdx.x;
    int w = tid>>5, lane = tid&31;
    int qr = lane>>2, qc = lane&3;
    int wy = w>>1, wx = w&1;
    int m0 = blockIdx.y*128, n0 = blockIdx.x*128;
    int lr = tid>>1, lh = tid&1;
    int lmr = lane & 15, lmc = lane >> 4;

    float acc[2][8][4];
    #pragma unroll
    for (int i=0;i<2;i++)
        #pragma unroll
        for (int j=0;j<8;j++)
            #pragma unroll
            for (int k=0;k<4;k++) acc[i][j][k]=0.f;

    const int NIT = K/32;
    auto load_stage = [&](int s, int b){
        int k0 = s*32;
        const __nv_bfloat16* ap = A + (size_t)(m0+lr)*K + k0 + lh*16;
        const __nv_bfloat16* bp = B + (size_t)(n0+lr)*K + k0 + lh*16;
        __nv_bfloat16* ad = As + b*128*GP + lr*GP + lh*16;
        __nv_bfloat16* bd = Bs + b*128*GP + lr*GP + lh*16;
        cpa16(ad,   ap);   cpa16(ad+8, ap+8);
        cpa16(bd,   bp);   cpa16(bd+8, bp+8);
        cpa_commit();
    };
    load_stage(0, 0);
    load_stage(1, 1);

    for (int it = 0; it < NIT; it++) {
        int cur = it % 3;
        cpa_wait1();
        __syncthreads();
        if (it+2 < NIT) load_stage(it+2, (it+2)%3);
        else            cpa_commit();
        const __nv_bfloat16* Ab = As + cur*128*GP;
        const __nv_bfloat16* Bb = Bs + cur*128*GP;
        #pragma unroll
        for (int ks=0; ks<2; ks++) {
            int kb = ks*16;
            unsigned af[2][4], bf[8][2];
            #pragma unroll
            for (int mt=0; mt<2; mt++)
                ldsm4(af[mt][0], af[mt][1], af[mt][2], af[mt][3],
                      &Ab[(wy*32 + mt*16 + lmr)*GP + kb + lmc*8]);
            #pragma unroll
            for (int ng=0; ng<4; ng++){
                unsigned r0,r1,r2,r3;
                ldsm4(r0,r1,r2,r3, &Bb[(wx*64 + ng*16 + lmr)*GP + kb + lmc*8]);
                bf[2*ng  ][0]=r0; bf[2*ng  ][1]=r2;
                bf[2*ng+1][0]=r1; bf[2*ng+1][1]=r3;
            }
            #pragma unroll
            for (int mt=0; mt<2; mt++)
                #pragma unroll
                for (int nt=0; nt<8; nt++)
                    mma_bf16(acc[mt][nt], af[mt], bf[nt]);
        }
    }
    #pragma unroll
    for (int mt=0; mt<2; mt++){
        #pragma unroll
        for (int nt=0; nt<8; nt++){
            int gr = m0 + wy*32 + mt*16 + qr;
            int gc = n0 + wx*64 + nt*8 + 2*qc;
            float bx = bias[gc], by = bias[gc+1];
            float c0 = acc[mt][nt][0]+bx, c1 = acc[mt][nt][1]+by;
            float c2 = acc[mt][nt][2]+bx, c3 = acc[mt][nt][3]+by;
            if (EPI==0){
                if (gc < DD){ c0*=QSCALE; c1*=QSCALE; c2*=QSCALE; c3*=QSCALE; }
                *(unsigned*)(Cb + (size_t)gr*N + gc)     = pack_h(c0,c1);
                *(unsigned*)(Cb + (size_t)(gr+8)*N + gc) = pack_h(c2,c3);
            }
            if (EPI==1){
                const float* r0 = res + (size_t)gr*N + gc;
                const float* r1 = res + (size_t)(gr+8)*N + gc;
                c0 += r0[0]; c1 += r0[1]; c2 += r1[0]; c3 += r1[1];
                float2 v0 = {c0,c1}, v1 = {c2,c3};
                *(float2*)(Cf + (size_t)gr*N + gc)     = v0;
                *(float2*)(Cf + (size_t)(gr+8)*N + gc) = v1;
                *(unsigned*)(Cb + (size_t)gr*N + gc)     = pack_bf(c0,c1);
                *(unsigned*)(Cb + (size_t)(gr+8)*N + gc) = pack_bf(c2,c3);
            }
        }
    }
}

// ============================================================
// 3) flash attention (best-measured config):
//    8 warps x 16 q-rows (256 thr), 64-key tiles, 3-stage cp.async,
//    S-MMA f16 acc -> ex2.f16x2 in place -> O-MMA f32 acc,
//    row sums via constant-ones B-fragment.
// ============================================================
#define AP 72
#define ATTN_SMEM (2*3*64*AP*2)
__global__ __launch_bounds__(256, 3)
void attn_bf() {
    extern __shared__ __align__(16) char dyn[];
    __nv_bfloat16* KsB = (__nv_bfloat16*)dyn;       // 3 x 64*AP  (K tiles)
    __nv_bfloat16* VsB = KsB + 3*64*AP;             // 3 x 64*AP  (V tiles)
    const __nv_bfloat16* qkv = g_qkv;
    int tid = threadIdx.x;
    int w = tid>>5, lane = tid&31;
    int qr = lane>>2, qc = lane&3;
    int lmr = lane & 15, lmc = lane >> 4;
    int b = blockIdx.y>>3, h = blockIdx.y&7;
    int q0 = blockIdx.x*128;
    size_t base = (size_t)b*SS*QKVD + (size_t)h*HDIM;

    // stage Q (128 rows) through buffer 0 of both arrays, pull frags
    {
        int lr = tid>>1, lh = tid&1;
        const uint4* qp = (const uint4*)(qkv + base + (size_t)(q0+lr)*QKVD + lh*32);
        uint4 v0 = qp[0], v1 = qp[1], v2 = qp[2], v3 = qp[3];
        __nv_bfloat16* dst = (lr < 64) ? &KsB[lr*AP + lh*32] : &VsB[(lr-64)*AP + lh*32];
        uint4* d = (uint4*)dst;
        d[0]=v0; d[1]=v1; d[2]=v2; d[3]=v3;
    }
    __syncthreads();
    unsigned qa[4][4];
    {
        const __nv_bfloat16* qbuf = (w < 4) ? KsB : VsB;
        int row16 = (w&3)*16;
        #pragma unroll
        for (int kc=0; kc<4; kc++)
            ldsm4(qa[kc][0], qa[kc][1], qa[kc][2], qa[kc][3],
                  &qbuf[(row16 + lmr)*AP + kc*16 + lmc*8]);
    }
    __syncthreads();

    float o[8][4];
    #pragma unroll
    for (int nt=0; nt<8; nt++){ o[nt][0]=0.f;o[nt][1]=0.f;o[nt][2]=0.f;o[nt][3]=0.f; }
    float lacc[4] = {0.f, 0.f, 0.f, 0.f};
    // constant ones B-fragment: column n=0 all-ones (lanes 0-3), rest zero
    unsigned bones = (lane < 4) ? 0x3C003C00u : 0u;
    unsigned bs[2] = {bones, bones};

    int kv  = tid >> 7;
    int krow = (tid & 127) >> 1;
    int khalf = tid & 1;
    size_t kvbase = base + (size_t)(1+kv)*DD;

    auto load_kv = [&](int kt, int bix){
        const __nv_bfloat16* src = qkv + kvbase + (size_t)(kt*64 + krow)*QKVD + khalf*32;
        __nv_bfloat16* dst = kv ? &VsB[bix*64*AP + krow*AP + khalf*32]
                                : &KsB[bix*64*AP + krow*AP + khalf*32];
        #pragma unroll
        for (int j=0;j<4;j++) cpa16(dst + j*8, src + j*8);
        cpa_commit();
    };
    load_kv(0, 0);
    load_kv(1, 1);

    const int NKT = SS/64;
    for (int kt=0; kt<NKT; kt++){
        int cur = kt % 3;
        cpa_wait1();
        __syncthreads();
        if (kt+2 < NKT) load_kv(kt+2, (kt+2)%3);
        else            cpa_commit();
        const __nv_bfloat16* Ks = KsB + cur*64*AP;
        const __nv_bfloat16* Vs = VsB + cur*64*AP;

        // S in f16 accumulator
        unsigned sacc[8][2];
        #pragma unroll
        for (int nt=0; nt<8; nt++){ sacc[nt][0]=0u; sacc[nt][1]=0u; }
        #pragma unroll
        for (int kc=0; kc<4; kc++){
            #pragma unroll
            for (int ng=0; ng<4; ng++){
                unsigned r0,r1,r2,r3;
                ldsm4(r0,r1,r2,r3, &Ks[(ng*16 + lmr)*AP + kc*16 + lmc*8]);
                unsigned bfa[2] = {r0, r2};
                unsigned bfb[2] = {r1, r3};
                mma_f16c16(sacc[2*ng  ], qa[kc], bfa);
                mma_f16c16(sacc[2*ng+1], qa[kc], bfb);
            }
        }
        // P = 2^S in place (output is directly the O-MMA A-fragment)
        #pragma unroll
        for (int nt=0; nt<8; nt++){
            sacc[nt][0] = ex2h2(sacc[nt][0]);
            sacc[nt][1] = ex2h2(sacc[nt][1]);
        }
        // O += P·V (f16 in, f32 acc); row sums via bones fragment
        #pragma unroll
        for (int kc=0; kc<4; kc++){
            unsigned pa[4];
            pa[0] = sacc[2*kc  ][0];
            pa[1] = sacc[2*kc  ][1];
            pa[2] = sacc[2*kc+1][0];
            pa[3] = sacc[2*kc+1][1];
            #pragma unroll
            for (int ng=0; ng<4; ng++){
                unsigned r0,r1,r2,r3;
                ldsm4t(r0,r1,r2,r3,
                       &Vs[(kc*16 + ((lane>>3)&1)*8 + (lane&7))*AP + ng*16 + (lane>>4)*8]);
                unsigned bfa[2] = {r0, r1};
                unsigned bfb[2] = {r2, r3};
                mma_f16(o[2*ng  ], pa, bfa);
                mma_f16(o[2*ng+1], pa, bfb);
            }
            mma_f16(lacc, pa, bs);
        }
    }
    // row sums live in column 0 (qc==0 lanes); broadcast
    float l0 = __shfl_sync(~0u, lacc[0], lane & ~3);
    float l1 = __shfl_sync(~0u, lacc[2], lane & ~3);
    float i0 = 1.f/l0, i1 = 1.f/l1;
    int sr = q0 + w*16 + qr;
    __nv_bfloat16* op = g_att + (size_t)(b*SS + sr)*DD + h*HDIM;
    #pragma unroll
    for (int nt=0; nt<8; nt++){
        *(unsigned*)(op + nt*8 + 2*qc)        = pack_bf(o[nt][0]*i0, o[nt][1]*i0);
        *(unsigned*)(op + 8*DD + nt*8 + 2*qc) = pack_bf(o[nt][2]*i1, o[nt][3]*i1);
    }
}

// ============================================================
// 4) fused MLP + gate (64-row / 512-thread version — best measured):
//    h = silu(xr@W1^T + b1) in regs, strength = sigmoid(h.w2+b2),
//    out = xr * strength.
// ============================================================
#define MLP_SMEM (3*64*GP*2 + 3*256*GP*2)
__global__ __launch_bounds__(512)
void mlp_gate(const __nv_bfloat16* __restrict__ A, const __nv_bfloat16* __restrict__ B,
              const float* __restrict__ b1, const float* __restrict__ w2,
              const float* __restrict__ b2, const float* __restrict__ xr,
              float* __restrict__ out) {
    extern __shared__ __align__(16) char dyn[];
    __nv_bfloat16* As = (__nv_bfloat16*)dyn;       // 3 x 64*GP
    __nv_bfloat16* Bs = As + 3*64*GP;              // 3 x 256*GP
    __shared__ float red[64][8];
    __shared__ float sgate_s[64];
    int tid = threadIdx.x;
    int w = tid>>5, lane = tid&31;
    int qr = lane>>2, qc = lane&3;
    int wy = w>>3, wx = w&7;
    int lmr = lane & 15, lmc = lane >> 4;
    int m0 = blockIdx.x*64;

    float acc[2][4][4];
    #pragma unroll
    for (int i=0;i<2;i++)
        #pragma unroll
        for (int j=0;j<4;j++)
            #pragma unroll
            for (int k=0;k<4;k++) acc[i][j][k]=0.f;

    auto load_stage = [&](int s, int bix){
        int k0 = s*32;
        {
            int row = tid>>1, half = tid&1;
            const __nv_bfloat16* bp = B + (size_t)row*DD + k0 + half*16;
            __nv_bfloat16* d = Bs + bix*256*GP + row*GP + half*16;
            cpa16(d, bp); cpa16(d+8, bp+8);
        }
        if (tid < 128){
            int row = tid>>1, half = tid&1;
            const __nv_bfloat16* ap = A + (size_t)(m0+row)*DD + k0 + half*16;
            __nv_bfloat16* d = As + bix*64*GP + row*GP + half*16;
            cpa16(d, ap); cpa16(d+8, ap+8);
        }
        cpa_commit();
    };
    load_stage(0, 0);
    load_stage(1, 1);

    const int NIT = DD/32;
    for (int it = 0; it < NIT; it++){
        int cur = it % 3;
        cpa_wait1();
        __syncthreads();
        if (it+2 < NIT) load_stage(it+2, (it+2)%3);
        else            cpa_commit();
        const __nv_bfloat16* Ab = As + cur*64*GP;
        const __nv_bfloat16* Bb = Bs + cur*256*GP;
        #pragma unroll
        for (int ks=0; ks<2; ks++){
            int kb = ks*16;
            unsigned af[2][4], bf[4][2];
            #pragma unroll
            for (int mt=0; mt<2; mt++)
                ldsm4(af[mt][0], af[mt][1], af[mt][2], af[mt][3],
                      &Ab[(wy*32 + mt*16 + lmr)*GP + kb + lmc*8]);
            #pragma unroll
            for (int ng=0; ng<2; ng++){
                unsigned r0,r1,r2,r3;
                ldsm4(r0,r1,r2,r3, &Bb[(wx*32 + ng*16 + lmr)*GP + kb + lmc*8]);
                bf[2*ng  ][0]=r0; bf[2*ng  ][1]=r2;
                bf[2*ng+1][0]=r1; bf[2*ng+1][1]=r3;
            }
            #pragma unroll
            for (int mt=0; mt<2; mt++)
                #pragma unroll
                for (int nt=0; nt<4; nt++)
                    mma_bf16(acc[mt][nt], af[mt], bf[nt]);
        }
    }

    #pragma unroll
    for (int mt=0; mt<2; mt++){
        float p0 = 0.f, p1 = 0.f;
        #pragma unroll
        for (int nt=0; nt<4; nt++){
            int gc = wx*32 + nt*8 + 2*qc;
            float w0 = w2[gc], w1v = w2[gc+1];
            float bx = b1[gc], by = b1[gc+1];
            float v0 = acc[mt][nt][0]+bx, v1 = acc[mt][nt][1]+by;
            float v2 = acc[mt][nt][2]+bx, v3 = acc[mt][nt][3]+by;
            v0 = v0/(1.f+__expf(-v0)); v1 = v1/(1.f+__expf(-v1));
            v2 = v2/(1.f+__expf(-v2)); v3 = v3/(1.f+__expf(-v3));
            p0 += v0*w0 + v1*w1v;
            p1 += v2*w0 + v3*w1v;
        }
        p0 += __shfl_xor_sync(~0u, p0, 1); p0 += __shfl_xor_sync(~0u, p0, 2);
        p1 += __shfl_xor_sync(~0u, p1, 1); p1 += __shfl_xor_sync(~0u, p1, 2);
        if (qc==0){
            red[wy*32 + mt*16 + qr][wx]     = p0;
            red[wy*32 + mt*16 + qr + 8][wx] = p1;
        }
    }
    __syncthreads();
    if (tid < 64){
        float tot = 0.f;
        #pragma unroll
        for (int j=0;j<8;j++) tot += red[tid][j];
        sgate_s[tid] = 1.f / (1.f + __expf(-(tot + b2[0])));
    }
    __syncthreads();
    {
        int row = tid>>3, seg = (tid&7)*64;
        float sg = sgate_s[row];
        const float4* xp = (const float4*)(xr + (size_t)(m0+row)*DD + seg);
        float4* op = (float4*)(out + (size_t)(m0+row)*DD + seg);
        #pragma unroll
        for (int i=0;i<16;i++){
            float4 v = xp[i];
            op[i] = make_float4(v.x*sg, v.y*sg, v.z*sg, v.w*sg);
        }
    }
}

// ============================================================
extern "C" void kernel_launch(void* const* d_in, const int* in_sizes, int n_in,
                              void* d_out, int out_size) {
    const float* x    = (const float*)d_in[0];
    const int*   gt   = (const int*)  d_in[1];
    const float* tf_g = (const float*)d_in[2];
    const float* tf_b = (const float*)d_in[3];
    const float* tg_g = (const float*)d_in[4];
    const float* tg_b = (const float*)d_in[5];
    const float* Wqkv = (const float*)d_in[6];
    const float* bqkv = (const float*)d_in[7];
    const float* Wo   = (const float*)d_in[8];
    const float* bo   = (const float*)d_in[9];
    const float* W1   = (const float*)d_in[10];
    const float* b1   = (const float*)d_in[11];
    const float* w2   = (const float*)d_in[12];
    const float* b2   = (const float*)d_in[13];
    float* out = (float*)d_out;

    float *xn, *xr;
    __nv_bfloat16 *xnh, *qkvp, *att, *xrh, *wqkvh, *woh, *w1h;
    cudaGetSymbolAddress((void**)&xn,    g_xn);
    cudaGetSymbolAddress((void**)&xnh,   g_xnh);
    cudaGetSymbolAddress((void**)&qkvp,  g_qkv);
    cudaGetSymbolAddress((void**)&att,   g_att);
    cudaGetSymbolAddress((void**)&xr,    g_xr);
    cudaGetSymbolAddress((void**)&xrh,   g_xrh);
    cudaGetSymbolAddress((void**)&wqkvh, g_wqkvh);
    cudaGetSymbolAddress((void**)&woh,   g_woh);
    cudaGetSymbolAddress((void**)&w1h,   g_w1h);

    static bool attr_done = false;
    if (!attr_done){
        cudaFuncSetAttribute(gemm_bf<0>, cudaFuncAttributeMaxDynamicSharedMemorySize, GEMM_SMEM);
        cudaFuncSetAttribute(gemm_bf<1>, cudaFuncAttributeMaxDynamicSharedMemorySize, GEMM_SMEM);
        cudaFuncSetAttribute(attn_bf,    cudaFuncAttributeMaxDynamicSharedMemorySize, ATTN_SMEM);
        cudaFuncSetAttribute(mlp_gate,   cudaFuncAttributeMaxDynamicSharedMemorySize, MLP_SMEM);
        attr_done = true;
    }

    // 1) fused weight conversion
    cvt_all<<<(NW1+NW2+NW3 + 255)/256, 256>>>((const float4*)Wqkv, (const float4*)Wo, (const float4*)W1);
    // 2) conditional LayerNorm
    ln_kernel<<<NT, 128>>>(x, gt, tf_g, tf_b, tg_g, tg_b);
    // 3) QKV projection (all fp16 out; Q pre-scaled by QSCALE)
    gemm_bf<0><<<dim3(QKVD/128, NT/128), 256, GEMM_SMEM>>>(xnh, wqkvh, bqkv, nullptr, nullptr, qkvp, QKVD, DD);
    // 4) flash attention
    attn_bf<<<dim3(SS/128, BB*HH), 256, ATTN_SMEM>>>();
    // 5) out projection + residual
    gemm_bf<1><<<dim3(DD/128, NT/128), 256, GEMM_SMEM>>>(att, woh, bo, xn, xr, xrh, DD, DD);
    // 6) fused MLP + gate -> out
    mlp_gate<<<NT/64, 512, MLP_SMEM>>>(xrh, w1h, b1, w2, b2, xr, out);
}